// round 10
// baseline (speedup 1.0000x reference)
#include <cuda_runtime.h>
#include <cuda_fp16.h>
#include <cstdint>

#define SEQ    2048
#define BATCH  4
#define DM     1024
#define NH     16
#define DH     64

// ---------------------------------------------------------------------------
// Scratch (allocation-free rule: __device__ globals)
// ---------------------------------------------------------------------------
__device__ __half g_qkv[(size_t)BATCH * SEQ * 3 * DM];   // [B,S,3D] fp16
__device__ __half g_attn[(size_t)BATCH * SEQ * DM];      // [B,S,D]  fp16
__device__ __half g_x[(size_t)BATCH * SEQ * DM];         // fp16(x)
__device__ __half g_winT[(size_t)3 * DM * DM];           // fp16(w_in)^T  [3D][D]
__device__ __half g_woutT[(size_t)DM * DM];              // fp16(w_out)^T [D][D]

#define NEG_INF (__int_as_float(0xff800000))
#define ONES_H2 0x3C003C00u

__device__ __forceinline__ float ex2(float x) {
    float y;
    asm("ex2.approx.f32 %0, %1;" : "=f"(y) : "f"(x));
    return y;
}
// packed fp16 exp2 of (a,b)
__device__ __forceinline__ uint32_t h2ex2(float a, float b) {
    __half2 h = __floats2half2_rn(a, b);
    uint32_t u = *reinterpret_cast<uint32_t*>(&h);
    uint32_t y;
    asm("ex2.approx.f16x2 %0, %1;" : "=r"(y) : "r"(u));
    return y;
}

__device__ __forceinline__ void mma_f16(float c[4],
    uint32_t a0, uint32_t a1, uint32_t a2, uint32_t a3,
    uint32_t b0, uint32_t b1)
{
    asm volatile(
        "mma.sync.aligned.m16n8k16.row.col.f32.f16.f16.f32 "
        "{%0,%1,%2,%3}, {%4,%5,%6,%7}, {%8,%9}, {%0,%1,%2,%3};\n"
        : "+f"(c[0]), "+f"(c[1]), "+f"(c[2]), "+f"(c[3])
        : "r"(a0), "r"(a1), "r"(a2), "r"(a3), "r"(b0), "r"(b1));
}

__device__ __forceinline__ void ldsm4(uint32_t* r, uint32_t addr) {
    asm volatile("ldmatrix.sync.aligned.m8n8.x4.shared.b16 {%0,%1,%2,%3}, [%4];"
        : "=r"(r[0]), "=r"(r[1]), "=r"(r[2]), "=r"(r[3]) : "r"(addr));
}
__device__ __forceinline__ void ldsm4t(uint32_t* r, uint32_t addr) {
    asm volatile("ldmatrix.sync.aligned.m8n8.x4.trans.shared.b16 {%0,%1,%2,%3}, [%4];"
        : "=r"(r[0]), "=r"(r[1]), "=r"(r[2]), "=r"(r[3]) : "r"(addr));
}

__device__ __forceinline__ void cp16(void* s, const void* g) {
    uint32_t sa = (uint32_t)__cvta_generic_to_shared(s);
    asm volatile("cp.async.cg.shared.global [%0], [%1], 16;\n" :: "r"(sa), "l"(g));
}
__device__ __forceinline__ void cp_commit() {
    asm volatile("cp.async.commit_group;\n");
}
template <int N>
__device__ __forceinline__ void cp_wait() {
    asm volatile("cp.async.wait_group %0;\n" :: "n"(N));
}
__device__ __forceinline__ uint32_t smem_u32(const void* p) {
    uint32_t a;
    asm("{ .reg .u64 t; cvta.to.shared.u64 t, %1; cvt.u32.u64 %0, t; }" : "=r"(a) : "l"(p));
    return a;
}

// ---------------------------------------------------------------------------
// Pre-passes: f32 -> fp16 convert; transpose+convert for weights
// ---------------------------------------------------------------------------
__global__ void f2h_kernel(const float* __restrict__ in,
                           __half* __restrict__ out, int n4)
{
    int i = blockIdx.x * blockDim.x + threadIdx.x;
    if (i < n4) {
        float4 v = ((const float4*)in)[i];
        ((__half2*)out)[2 * i]     = __floats2half2_rn(v.x, v.y);
        ((__half2*)out)[2 * i + 1] = __floats2half2_rn(v.z, v.w);
    }
}

// out[C][R] = fp16(in[R][C])^T ; block (32,8), grid (C/32, R/32)
__global__ void transpose_f2h_kernel(const float* __restrict__ in,
                                     __half* __restrict__ out, int R, int C)
{
    __shared__ float t[32][33];
    int bx = blockIdx.x * 32;
    int by = blockIdx.y * 32;
    #pragma unroll
    for (int i = threadIdx.y; i < 32; i += 8)
        t[i][threadIdx.x] = in[(size_t)(by + i) * C + bx + threadIdx.x];
    __syncthreads();
    #pragma unroll
    for (int i = threadIdx.y; i < 32; i += 8)
        out[(size_t)(bx + i) * R + by + threadIdx.x] = __float2half(t[threadIdx.x][i]);
}

// ---------------------------------------------------------------------------
// GEMM: C[M,N] = A[M,1024] @ Bt[N,1024]^T + bias[N]  (fp16 mma + ldmatrix)
// CTA tile 128x128, BK=64, 3-stage cp.async ring, 256 threads
// (8 warps 2Mx4N, warp tile 64x32). Fragment-level double buffering:
// step s+1's ldmatrix issues before step s's MMAs.
// ---------------------------------------------------------------------------
#define GK DM                            // K = 1024, compile-time
#define TLD 72
#define STG_H (128 * TLD * 2)            // halves per stage (A then B)
#define GEMM_SMEM (3 * STG_H * 2)        // 110592 bytes

template<int N, int HALF_OUT>
__global__ __launch_bounds__(256, 2)
void gemm_tc(const __half* __restrict__ A, const __half* __restrict__ Bt,
             const float* __restrict__ bias, void* __restrict__ Cv)
{
    extern __shared__ __align__(16) __half sm[];

    const int tid  = threadIdx.x;
    const int warp = tid >> 5;
    const int lane = tid & 31;
    const int g    = lane >> 2;
    const int tg   = lane & 3;
    const int wm   = (warp >> 2) * 64;
    const int wn   = (warp & 3) * 32;
    const int bm0  = blockIdx.y * 128;
    const int bn0  = blockIdx.x * 128;

    float acc[4][4][4];
    #pragma unroll
    for (int mt = 0; mt < 4; mt++)
        #pragma unroll
        for (int j = 0; j < 4; j++)
            #pragma unroll
            for (int e = 0; e < 4; e++) acc[mt][j][e] = 0.f;

    const int lr = tid >> 3;
    const int lc = (tid & 7) << 3;
    const __half* aG = A + (size_t)(bm0 + lr) * GK + lc;
    const __half* bG = Bt + (size_t)(bn0 + lr) * GK + lc;

    auto load_stage = [&](int slot, int kt) {
        __half* As = sm + slot * STG_H + lr * TLD + lc;
        __half* Bs = As + 128 * TLD;
        const __half* ag = aG + kt;
        const __half* bg = bG + kt;
        #pragma unroll
        for (int i = 0; i < 4; i++)
            cp16(As + i * (32 * TLD), ag + i * (32 * GK));
        #pragma unroll
        for (int i = 0; i < 4; i++)
            cp16(Bs + i * (32 * TLD), bg + i * (32 * GK));
    };

    load_stage(0, 0);  cp_commit();
    load_stage(1, 64); cp_commit();

    const uint32_t sbase = smem_u32(sm);
    const uint32_t aOff = ((wm + (lane & 15)) * TLD + ((lane >> 4) << 3)) * 2;
    const uint32_t bOff = (uint32_t)(128 * TLD * 2) +
                          ((wn + (lane & 15)) * TLD + ((lane >> 4) << 3)) * 2;

    // ping-pong fragment buffers
    uint32_t af[2][4][4];
    uint32_t bf[2][2][4];

    auto ld_frags = [&](int bufi, int step, uint32_t stg) {
        #pragma unroll
        for (int mt = 0; mt < 4; mt++)
            ldsm4(af[bufi][mt], stg + aOff + (uint32_t)(mt * 16 * TLD * 2 + step * 32));
        #pragma unroll
        for (int jp = 0; jp < 2; jp++)
            ldsm4(bf[bufi][jp], stg + bOff + (uint32_t)(jp * 16 * TLD * 2 + step * 32));
    };

    const int T = GK / 64;                // 16
    for (int t = 0; t < T; t++) {
        cp_wait<1>();
        __syncthreads();

        int tn = t + 2;
        if (tn < T) load_stage(tn % 3, tn * 64);
        cp_commit();

        const uint32_t stg = sbase + (uint32_t)((t % 3) * STG_H * 2);

        ld_frags(0, 0, stg);
        #pragma unroll
        for (int step = 0; step < 4; step++) {
            if (step < 3) ld_frags((step + 1) & 1, step + 1, stg);
            const int cb = step & 1;
            #pragma unroll
            for (int mt = 0; mt < 4; mt++) {
                #pragma unroll
                for (int jp = 0; jp < 2; jp++) {
                    mma_f16(acc[mt][jp * 2],
                            af[cb][mt][0], af[cb][mt][1], af[cb][mt][2], af[cb][mt][3],
                            bf[cb][jp][0], bf[cb][jp][2]);
                    mma_f16(acc[mt][jp * 2 + 1],
                            af[cb][mt][0], af[cb][mt][1], af[cb][mt][2], af[cb][mt][3],
                            bf[cb][jp][1], bf[cb][jp][3]);
                }
            }
        }
    }

    #pragma unroll
    for (int mt = 0; mt < 4; mt++) {
        int r0 = bm0 + wm + mt * 16 + g;
        #pragma unroll
        for (int j = 0; j < 4; j++) {
            int c0 = bn0 + wn + j * 8 + tg * 2;
            float2 bb = *(const float2*)(bias + c0);
            float o00 = acc[mt][j][0] + bb.x, o01 = acc[mt][j][1] + bb.y;
            float o10 = acc[mt][j][2] + bb.x, o11 = acc[mt][j][3] + bb.y;
            if (HALF_OUT) {
                __half* C = (__half*)Cv;
                *(__half2*)(C + (size_t)r0 * N + c0) = __floats2half2_rn(o00, o01);
                *(__half2*)(C + (size_t)(r0 + 8) * N + c0) = __floats2half2_rn(o10, o11);
            } else {
                float* C = (float*)Cv;
                *(float2*)(C + (size_t)r0 * N + c0) = make_float2(o00, o01);
                *(float2*)(C + (size_t)(r0 + 8) * N + c0) = make_float2(o10, o11);
            }
        }
    }
}

// ---------------------------------------------------------------------------
// Flash attention (fp16, unchanged from R9): 128 queries x (b*h), 256 thr.
// Q/K/P via ldmatrix, V via ldmatrix.trans. ex2.f16x2 P; ones-MMA row sums.
// ---------------------------------------------------------------------------
#define BQ 128
#define ALD 72
#define KBUF (64 * ALD)
#define ATTN_SMEM ((BQ * ALD + 4 * KBUF) * 2)

__device__ __forceinline__ void attn_load_kv(
    __half* sK, __half* sV, const __half* __restrict__ kbase,
    const __half* __restrict__ vbase, int tid)
{
    #pragma unroll
    for (int i = 0; i < 2; i++) {
        int idx = tid + i * 256;
        int r = idx >> 3, c = (idx & 7) << 3;
        cp16(sK + r * ALD + c, kbase + (size_t)r * (3 * DM) + c);
    }
    #pragma unroll
    for (int i = 0; i < 2; i++) {
        int idx = tid + i * 256;
        int r = idx >> 3, c = (idx & 7) << 3;
        cp16(sV + r * ALD + c, vbase + (size_t)r * (3 * DM) + c);
    }
}

__global__ __launch_bounds__(256, 2)
void attn_kernel()
{
    extern __shared__ __align__(16) __half sh[];
    __half* sQP = sh;
    __half* sK0 = sh + BQ * ALD;
    __half* sV0 = sK0 + 2 * KBUF;

    const int tid  = threadIdx.x;
    const int warp = tid >> 5;
    const int lane = tid & 31;
    const int g    = lane >> 2;
    const int tg   = lane & 3;
    const int qt   = gridDim.x - 1 - blockIdx.x;   // big tiles first
    const int bh   = blockIdx.y;
    const int b    = bh >> 4;
    const int h    = bh & 15;
    const int q0   = qt * BQ;

    const float SCALE2 = 0.18033688011f;   // (1/8) * log2(e)

    const __half* base = g_qkv + (size_t)b * SEQ * (3 * DM) + h * DH;

    #pragma unroll
    for (int i = 0; i < 4; i++) {
        int idx = tid + i * 256;
        int r = idx >> 3, c = (idx & 7) << 3;
        cp16(sQP + r * ALD + c, base + (size_t)(q0 + r) * (3 * DM) + c);
    }
    cp_commit();
    attn_load_kv(sK0, sV0, base + DM, base + 2 * DM, tid);
    cp_commit();
    cp_wait<0>();
    __syncthreads();

    const uint32_t sbase = smem_u32(sh);
    const uint32_t pBase = sbase +
        (uint32_t)(((warp * 16 + (lane & 15)) * ALD + ((lane >> 4) << 3)) * 2);
    const uint32_t kLane = (uint32_t)((((lane & 15)) * ALD + ((lane >> 4) << 3)) * 2);
    const uint32_t vLane = (uint32_t)(
        (((lane & 7) + ((lane >> 3) & 1) * 8) * ALD) * 2 + ((lane >> 4) << 4));

    uint32_t qf[4][4];
    #pragma unroll
    for (int st = 0; st < 4; st++)
        ldsm4(qf[st], pBase + (uint32_t)(st * 32));

    float o[8][4];
    #pragma unroll
    for (int j = 0; j < 8; j++)
        #pragma unroll
        for (int e = 0; e < 4; e++) o[j][e] = 0.f;
    float m0 = NEG_INF, m1 = NEG_INF, l0 = 0.f, l1 = 0.f;

    const int tiles = 2 * qt + 2;
    for (int kt = 0; kt < tiles; kt++) {
        if (kt + 1 < tiles) {
            const __half* kb = base + DM + (size_t)(kt + 1) * 64 * (3 * DM);
            attn_load_kv(sK0 + ((kt + 1) & 1) * KBUF, sV0 + ((kt + 1) & 1) * KBUF,
                         kb, kb + DM, tid);
            cp_commit();
        }

        const uint32_t kB = sbase + (uint32_t)((BQ * ALD + (kt & 1) * KBUF) * 2) + kLane;
        const uint32_t vB = sbase + (uint32_t)((BQ * ALD + 2 * KBUF + (kt & 1) * KBUF) * 2) + vLane;

        float c_[8][4];
        #pragma unroll
        for (int j = 0; j < 8; j++)
            #pragma unroll
            for (int e = 0; e < 4; e++) c_[j][e] = 0.f;

        #pragma unroll
        for (int st = 0; st < 4; st++) {
            #pragma unroll
            for (int jp = 0; jp < 4; jp++) {
                uint32_t bf[4];
                ldsm4(bf, kB + (uint32_t)(jp * 16 * ALD * 2 + st * 32));
                mma_f16(c_[jp * 2],     qf[st][0], qf[st][1], qf[st][2], qf[st][3],
                        bf[0], bf[2]);
                mma_f16(c_[jp * 2 + 1], qf[st][0], qf[st][1], qf[st][2], qf[st][3],
                        bf[1], bf[3]);
            }
        }

        if (kt >= 2 * qt) {
            #pragma unroll
            for (int j = 0; j < 8; j++) {
                #pragma unroll
                for (int e = 0; e < 4; e++) {
                    int col = kt * 64 + j * 8 + tg * 2 + (e & 1);
                    int row = q0 + warp * 16 + g + (e >> 1) * 8;
                    c_[j][e] = (col > row) ? NEG_INF : c_[j][e] * SCALE2;
                }
            }
        } else {
            #pragma unroll
            for (int j = 0; j < 8; j++)
                #pragma unroll
                for (int e = 0; e < 4; e++) c_[j][e] *= SCALE2;
        }

        float rx0 = NEG_INF, rx1 = NEG_INF;
        #pragma unroll
        for (int j = 0; j < 8; j++) {
            rx0 = fmaxf(rx0, fmaxf(c_[j][0], c_[j][1]));
            rx1 = fmaxf(rx1, fmaxf(c_[j][2], c_[j][3]));
        }
        rx0 = fmaxf(rx0, __shfl_xor_sync(0xffffffffu, rx0, 1));
        rx0 = fmaxf(rx0, __shfl_xor_sync(0xffffffffu, rx0, 2));
        rx1 = fmaxf(rx1, __shfl_xor_sync(0xffffffffu, rx1, 1));
        rx1 = fmaxf(rx1, __shfl_xor_sync(0xffffffffu, rx1, 2));

        float mn0 = fmaxf(m0, rx0), mn1 = fmaxf(m1, rx1);
        float al0 = ex2(m0 - mn0), al1 = ex2(m1 - mn1);
        m0 = mn0; m1 = mn1;

        {
            const int rl = warp * 16 + g;
            #pragma unroll
            for (int j = 0; j < 8; j++) {
                *(uint32_t*)(sQP + rl * ALD + j * 8 + tg * 2) =
                    h2ex2(c_[j][0] - mn0, c_[j][1] - mn0);
                *(uint32_t*)(sQP + (rl + 8) * ALD + j * 8 + tg * 2) =
                    h2ex2(c_[j][2] - mn1, c_[j][3] - mn1);
            }
        }
        #pragma unroll
        for (int j = 0; j < 8; j++) {
            o[j][0] *= al0; o[j][1] *= al0;
            o[j][2] *= al1; o[j][3] *= al1;
        }
        __syncwarp();

        float ls[4] = {0.f, 0.f, 0.f, 0.f};
        #pragma unroll
        for (int st = 0; st < 4; st++) {
            uint32_t pf[4];
            ldsm4(pf, pBase + (uint32_t)(st * 32));
            mma_f16(ls, pf[0], pf[1], pf[2], pf[3], ONES_H2, ONES_H2);
            #pragma unroll
            for (int jp = 0; jp < 4; jp++) {
                uint32_t vf[4];
                ldsm4t(vf, vB + (uint32_t)(st * 16 * ALD * 2 + jp * 32));
                mma_f16(o[jp * 2],     pf[0], pf[1], pf[2], pf[3], vf[0], vf[1]);
                mma_f16(o[jp * 2 + 1], pf[0], pf[1], pf[2], pf[3], vf[2], vf[3]);
            }
        }
        __syncwarp();

        l0 = l0 * al0 + ls[0];
        l1 = l1 * al1 + ls[2];

        if (kt + 1 < tiles) {
            cp_wait<0>();
            __syncthreads();
        }
    }

    const float inv0 = 1.f / l0, inv1 = 1.f / l1;
    const int srow = q0 + warp * 16 + g;
    __half* out0 = g_attn + ((size_t)b * SEQ + srow) * DM + h * DH;
    __half* out1 = g_attn + ((size_t)b * SEQ + srow + 8) * DM + h * DH;
    #pragma unroll
    for (int j = 0; j < 8; j++) {
        int cl = j * 8 + tg * 2;
        *(__half2*)(out0 + cl) = __floats2half2_rn(o[j][0] * inv0, o[j][1] * inv0);
        *(__half2*)(out1 + cl) = __floats2half2_rn(o[j][2] * inv1, o[j][3] * inv1);
    }
}

// ---------------------------------------------------------------------------
// Launch
// ---------------------------------------------------------------------------
extern "C" void kernel_launch(void* const* d_in, const int* in_sizes, int n_in,
                              void* d_out, int out_size)
{
    (void)in_sizes; (void)n_in; (void)out_size;
    const float* x     = (const float*)d_in[0];
    const float* w_in  = (const float*)d_in[1];
    const float* b_in  = (const float*)d_in[2];
    const float* w_out = (const float*)d_in[3];
    const float* b_out = (const float*)d_in[4];
    float* out = (float*)d_out;

    __half *qkv, *attn, *xh, *winT, *woutT;
    cudaGetSymbolAddress((void**)&qkv,   g_qkv);
    cudaGetSymbolAddress((void**)&attn,  g_attn);
    cudaGetSymbolAddress((void**)&xh,    g_x);
    cudaGetSymbolAddress((void**)&winT,  g_winT);
    cudaGetSymbolAddress((void**)&woutT, g_woutT);

    const int M = BATCH * SEQ;  // 8192

    cudaFuncSetAttribute(gemm_tc<3 * DM, 1>, cudaFuncAttributeMaxDynamicSharedMemorySize, GEMM_SMEM);
    cudaFuncSetAttribute(gemm_tc<DM, 0>,     cudaFuncAttributeMaxDynamicSharedMemorySize, GEMM_SMEM);
    cudaFuncSetAttribute(attn_kernel, cudaFuncAttributeMaxDynamicSharedMemorySize, ATTN_SMEM);

    // 0) convert x to fp16; transpose+convert weights
    {
        int n4 = (M * DM) / 4;
        f2h_kernel<<<(n4 + 255) / 256, 256>>>(x, xh, n4);
        transpose_f2h_kernel<<<dim3((3 * DM) / 32, DM / 32), dim3(32, 8)>>>(
            w_in, winT, DM, 3 * DM);
        transpose_f2h_kernel<<<dim3(DM / 32, DM / 32), dim3(32, 8)>>>(
            w_out, woutT, DM, DM);
    }

    // 1) QKV projection (fp16 output)
    gemm_tc<3 * DM, 1><<<dim3((3 * DM) / 128, M / 128), 256, GEMM_SMEM>>>(
        xh, winT, b_in, qkv);

    // 2) causal flash attention (fp16 output)
    attn_kernel<<<dim3(SEQ / BQ, BATCH * NH), 256, ATTN_SMEM>>>();

    // 3) output projection (f32 output)
    gemm_tc<DM, 0><<<dim3(DM / 128, M / 128), 256, GEMM_SMEM>>>(
        attn, woutT, b_out, out);
}

// round 11
// speedup vs baseline: 1.0181x; 1.0181x over previous
#include <cuda_runtime.h>
#include <cuda_fp16.h>
#include <cstdint>

#define SEQ    2048
#define BATCH  4
#define DM     1024
#define NH     16
#define DH     64

// ---------------------------------------------------------------------------
// Scratch (allocation-free rule: __device__ globals)
// ---------------------------------------------------------------------------
__device__ __half g_qkv[(size_t)BATCH * SEQ * 3 * DM];   // [B,S,3D] fp16
__device__ __half g_attn[(size_t)BATCH * SEQ * DM];      // [B,S,D]  fp16
__device__ __half g_x[(size_t)BATCH * SEQ * DM];         // fp16(x)
__device__ __half g_winT[(size_t)3 * DM * DM];           // fp16(w_in)^T  [3D][D]
__device__ __half g_woutT[(size_t)DM * DM];              // fp16(w_out)^T [D][D]

#define NEG_INF (__int_as_float(0xff800000))
#define ONES_H2 0x3C003C00u

__device__ __forceinline__ float ex2(float x) {
    float y;
    asm("ex2.approx.f32 %0, %1;" : "=f"(y) : "f"(x));
    return y;
}
__device__ __forceinline__ uint32_t h2ex2u(uint32_t u) {
    uint32_t y;
    asm("ex2.approx.f16x2 %0, %1;" : "=r"(y) : "r"(u));
    return y;
}
__device__ __forceinline__ uint32_t h2ex2(float a, float b) {
    __half2 h = __floats2half2_rn(a, b);
    return h2ex2u(*reinterpret_cast<uint32_t*>(&h));
}

// fp32-accumulate HMMA
__device__ __forceinline__ void mma_f16(float c[4],
    uint32_t a0, uint32_t a1, uint32_t a2, uint32_t a3,
    uint32_t b0, uint32_t b1)
{
    asm volatile(
        "mma.sync.aligned.m16n8k16.row.col.f32.f16.f16.f32 "
        "{%0,%1,%2,%3}, {%4,%5,%6,%7}, {%8,%9}, {%0,%1,%2,%3};\n"
        : "+f"(c[0]), "+f"(c[1]), "+f"(c[2]), "+f"(c[3])
        : "r"(a0), "r"(a1), "r"(a2), "r"(a3), "r"(b0), "r"(b1));
}
// fp16-accumulate HMMA (C packed: c[0]=row g cols 2tg..2tg+1, c[1]=row g+8)
__device__ __forceinline__ void mma_f16c16(uint32_t c[2],
    uint32_t a0, uint32_t a1, uint32_t a2, uint32_t a3,
    uint32_t b0, uint32_t b1)
{
    asm volatile(
        "mma.sync.aligned.m16n8k16.row.col.f16.f16.f16.f16 "
        "{%0,%1}, {%2,%3,%4,%5}, {%6,%7}, {%0,%1};\n"
        : "+r"(c[0]), "+r"(c[1])
        : "r"(a0), "r"(a1), "r"(a2), "r"(a3), "r"(b0), "r"(b1));
}

__device__ __forceinline__ void ldsm4(uint32_t* r, uint32_t addr) {
    asm volatile("ldmatrix.sync.aligned.m8n8.x4.shared.b16 {%0,%1,%2,%3}, [%4];"
        : "=r"(r[0]), "=r"(r[1]), "=r"(r[2]), "=r"(r[3]) : "r"(addr));
}
__device__ __forceinline__ void ldsm4t(uint32_t* r, uint32_t addr) {
    asm volatile("ldmatrix.sync.aligned.m8n8.x4.trans.shared.b16 {%0,%1,%2,%3}, [%4];"
        : "=r"(r[0]), "=r"(r[1]), "=r"(r[2]), "=r"(r[3]) : "r"(addr));
}

__device__ __forceinline__ void cp16(void* s, const void* g) {
    uint32_t sa = (uint32_t)__cvta_generic_to_shared(s);
    asm volatile("cp.async.cg.shared.global [%0], [%1], 16;\n" :: "r"(sa), "l"(g));
}
__device__ __forceinline__ void cp_commit() {
    asm volatile("cp.async.commit_group;\n");
}
template <int N>
__device__ __forceinline__ void cp_wait() {
    asm volatile("cp.async.wait_group %0;\n" :: "n"(N));
}
__device__ __forceinline__ uint32_t smem_u32(const void* p) {
    uint32_t a;
    asm("{ .reg .u64 t; cvta.to.shared.u64 t, %1; cvt.u32.u64 %0, t; }" : "=r"(a) : "l"(p));
    return a;
}

// ---------------------------------------------------------------------------
// Pre-passes
// ---------------------------------------------------------------------------
__global__ void f2h_kernel(const float* __restrict__ in,
                           __half* __restrict__ out, int n4)
{
    int i = blockIdx.x * blockDim.x + threadIdx.x;
    if (i < n4) {
        float4 v = ((const float4*)in)[i];
        ((__half2*)out)[2 * i]     = __floats2half2_rn(v.x, v.y);
        ((__half2*)out)[2 * i + 1] = __floats2half2_rn(v.z, v.w);
    }
}

__global__ void transpose_f2h_kernel(const float* __restrict__ in,
                                     __half* __restrict__ out, int R, int C)
{
    __shared__ float t[32][33];
    int bx = blockIdx.x * 32;
    int by = blockIdx.y * 32;
    #pragma unroll
    for (int i = threadIdx.y; i < 32; i += 8)
        t[i][threadIdx.x] = in[(size_t)(by + i) * C + bx + threadIdx.x];
    __syncthreads();
    #pragma unroll
    for (int i = threadIdx.y; i < 32; i += 8)
        out[(size_t)(bx + i) * R + by + threadIdx.x] = __float2half(t[threadIdx.x][i]);
}

// ---------------------------------------------------------------------------
// GEMM (R9 body): C[M,N] = A[M,1024] @ Bt[N,1024]^T + bias[N]
// ---------------------------------------------------------------------------
#define GK DM
#define TLD 72
#define STG_H (128 * TLD * 2)
#define GEMM_SMEM (3 * STG_H * 2)

template<int N, int HALF_OUT>
__global__ __launch_bounds__(256, 2)
void gemm_tc(const __half* __restrict__ A, const __half* __restrict__ Bt,
             const float* __restrict__ bias, void* __restrict__ Cv)
{
    extern __shared__ __align__(16) __half sm[];

    const int tid  = threadIdx.x;
    const int warp = tid >> 5;
    const int lane = tid & 31;
    const int g    = lane >> 2;
    const int tg   = lane & 3;
    const int wm   = (warp >> 2) * 64;
    const int wn   = (warp & 3) * 32;
    const int bm0  = blockIdx.y * 128;
    const int bn0  = blockIdx.x * 128;

    float acc[4][4][4];
    #pragma unroll
    for (int mt = 0; mt < 4; mt++)
        #pragma unroll
        for (int j = 0; j < 4; j++)
            #pragma unroll
            for (int e = 0; e < 4; e++) acc[mt][j][e] = 0.f;

    const int lr = tid >> 3;
    const int lc = (tid & 7) << 3;
    const __half* aG = A + (size_t)(bm0 + lr) * GK + lc;
    const __half* bG = Bt + (size_t)(bn0 + lr) * GK + lc;

    auto load_stage = [&](int slot, int kt) {
        __half* As = sm + slot * STG_H + lr * TLD + lc;
        __half* Bs = As + 128 * TLD;
        const __half* ag = aG + kt;
        const __half* bg = bG + kt;
        #pragma unroll
        for (int i = 0; i < 4; i++)
            cp16(As + i * (32 * TLD), ag + i * (32 * GK));
        #pragma unroll
        for (int i = 0; i < 4; i++)
            cp16(Bs + i * (32 * TLD), bg + i * (32 * GK));
    };

    load_stage(0, 0);  cp_commit();
    load_stage(1, 64); cp_commit();

    const uint32_t sbase = smem_u32(sm);
    const uint32_t aOff = ((wm + (lane & 15)) * TLD + ((lane >> 4) << 3)) * 2;
    const uint32_t bOff = (uint32_t)(128 * TLD * 2) +
                          ((wn + (lane & 15)) * TLD + ((lane >> 4) << 3)) * 2;

    const int T = GK / 64;
    for (int t = 0; t < T; t++) {
        cp_wait<1>();
        __syncthreads();

        int tn = t + 2;
        if (tn < T) load_stage(tn % 3, tn * 64);
        cp_commit();

        const uint32_t stg = sbase + (uint32_t)((t % 3) * STG_H * 2);

        #pragma unroll
        for (int step = 0; step < 4; step++) {
            uint32_t af[4][4];
            #pragma unroll
            for (int mt = 0; mt < 4; mt++)
                ldsm4(af[mt], stg + aOff + (uint32_t)(mt * 16 * TLD * 2 + step * 32));
            uint32_t bf[2][4];
            #pragma unroll
            for (int jp = 0; jp < 2; jp++)
                ldsm4(bf[jp], stg + bOff + (uint32_t)(jp * 16 * TLD * 2 + step * 32));
            #pragma unroll
            for (int mt = 0; mt < 4; mt++) {
                #pragma unroll
                for (int jp = 0; jp < 2; jp++) {
                    mma_f16(acc[mt][jp * 2],     af[mt][0], af[mt][1], af[mt][2], af[mt][3],
                            bf[jp][0], bf[jp][2]);
                    mma_f16(acc[mt][jp * 2 + 1], af[mt][0], af[mt][1], af[mt][2], af[mt][3],
                            bf[jp][1], bf[jp][3]);
                }
            }
        }
    }

    #pragma unroll
    for (int mt = 0; mt < 4; mt++) {
        int r0 = bm0 + wm + mt * 16 + g;
        #pragma unroll
        for (int j = 0; j < 4; j++) {
            int c0 = bn0 + wn + j * 8 + tg * 2;
            float2 bb = *(const float2*)(bias + c0);
            float o00 = acc[mt][j][0] + bb.x, o01 = acc[mt][j][1] + bb.y;
            float o10 = acc[mt][j][2] + bb.x, o11 = acc[mt][j][3] + bb.y;
            if (HALF_OUT) {
                __half* C = (__half*)Cv;
                *(__half2*)(C + (size_t)r0 * N + c0) = __floats2half2_rn(o00, o01);
                *(__half2*)(C + (size_t)(r0 + 8) * N + c0) = __floats2half2_rn(o10, o11);
            } else {
                float* C = (float*)Cv;
                *(float2*)(C + (size_t)r0 * N + c0) = make_float2(o00, o01);
                *(float2*)(C + (size_t)(r0 + 8) * N + c0) = make_float2(o10, o11);
            }
        }
    }
}

// ---------------------------------------------------------------------------
// Flash attention: QK^T in fp16-accum HMMA; softmax front-end in packed fp16;
// PV in fp32-accum; ones-MMA row sums; warps 0-3 skip the fully-masked tile.
// ---------------------------------------------------------------------------
#define BQ 128
#define ALD 72
#define KBUF (64 * ALD)
#define ATTN_SMEM ((BQ * ALD + 4 * KBUF) * 2)

__device__ __forceinline__ void attn_load_kv(
    __half* sK, __half* sV, const __half* __restrict__ kbase,
    const __half* __restrict__ vbase, int tid)
{
    #pragma unroll
    for (int i = 0; i < 2; i++) {
        int idx = tid + i * 256;
        int r = idx >> 3, c = (idx & 7) << 3;
        cp16(sK + r * ALD + c, kbase + (size_t)r * (3 * DM) + c);
    }
    #pragma unroll
    for (int i = 0; i < 2; i++) {
        int idx = tid + i * 256;
        int r = idx >> 3, c = (idx & 7) << 3;
        cp16(sV + r * ALD + c, vbase + (size_t)r * (3 * DM) + c);
    }
}

__global__ __launch_bounds__(256, 2)
void attn_kernel()
{
    extern __shared__ __align__(16) __half sh[];
    __half* sQP = sh;
    __half* sK0 = sh + BQ * ALD;
    __half* sV0 = sK0 + 2 * KBUF;

    const int tid  = threadIdx.x;
    const int warp = tid >> 5;
    const int lane = tid & 31;
    const int g    = lane >> 2;
    const int tg   = lane & 3;
    const int qt   = gridDim.x - 1 - blockIdx.x;   // big tiles first
    const int bh   = blockIdx.y;
    const int b    = bh >> 4;
    const int h    = bh & 15;
    const int q0   = qt * BQ;

    const float SCALE2 = 0.18033688011f;   // (1/8) * log2(e)
    const __half2 sc2 = __float2half2_rn(SCALE2);

    const __half* base = g_qkv + (size_t)b * SEQ * (3 * DM) + h * DH;

    #pragma unroll
    for (int i = 0; i < 4; i++) {
        int idx = tid + i * 256;
        int r = idx >> 3, c = (idx & 7) << 3;
        cp16(sQP + r * ALD + c, base + (size_t)(q0 + r) * (3 * DM) + c);
    }
    cp_commit();
    attn_load_kv(sK0, sV0, base + DM, base + 2 * DM, tid);
    cp_commit();
    cp_wait<0>();
    __syncthreads();

    const uint32_t sbase = smem_u32(sh);
    const uint32_t pBase = sbase +
        (uint32_t)(((warp * 16 + (lane & 15)) * ALD + ((lane >> 4) << 3)) * 2);
    const uint32_t kLane = (uint32_t)((((lane & 15)) * ALD + ((lane >> 4) << 3)) * 2);
    const uint32_t vLane = (uint32_t)(
        (((lane & 7) + ((lane >> 3) & 1) * 8) * ALD) * 2 + ((lane >> 4) << 4));

    uint32_t qf[4][4];
    #pragma unroll
    for (int st = 0; st < 4; st++)
        ldsm4(qf[st], pBase + (uint32_t)(st * 32));

    float o[8][4];
    #pragma unroll
    for (int j = 0; j < 8; j++)
        #pragma unroll
        for (int e = 0; e < 4; e++) o[j][e] = 0.f;
    float m0 = NEG_INF, m1 = NEG_INF, l0 = 0.f, l1 = 0.f;

    const int tiles = 2 * qt + 2;
    for (int kt = 0; kt < tiles; kt++) {
        if (kt + 1 < tiles) {
            const __half* kb = base + DM + (size_t)(kt + 1) * 64 * (3 * DM);
            attn_load_kv(sK0 + ((kt + 1) & 1) * KBUF, sV0 + ((kt + 1) & 1) * KBUF,
                         kb, kb + DM, tid);
            cp_commit();
        }

        // warps 0-3: final tile (cols q0+64..q0+127 vs rows q0..q0+63) fully masked
        const bool active = !(warp < 4 && kt == tiles - 1);

        if (active) {
            const uint32_t kB = sbase + (uint32_t)((BQ * ALD + (kt & 1) * KBUF) * 2) + kLane;
            const uint32_t vB = sbase + (uint32_t)((BQ * ALD + 2 * KBUF + (kt & 1) * KBUF) * 2) + vLane;

            // S = Q @ K^T  (fp16 accumulators)
            uint32_t chh[8][2];
            #pragma unroll
            for (int j = 0; j < 8; j++) { chh[j][0] = 0u; chh[j][1] = 0u; }

            #pragma unroll
            for (int st = 0; st < 4; st++) {
                #pragma unroll
                for (int jp = 0; jp < 4; jp++) {
                    uint32_t bf[4];
                    ldsm4(bf, kB + (uint32_t)(jp * 16 * ALD * 2 + st * 32));
                    mma_f16c16(chh[jp * 2],     qf[st][0], qf[st][1], qf[st][2], qf[st][3],
                               bf[0], bf[2]);
                    mma_f16c16(chh[jp * 2 + 1], qf[st][0], qf[st][1], qf[st][2], qf[st][3],
                               bf[1], bf[3]);
                }
            }

            float mn0, mn1, al0, al1;
            const int rl = warp * 16 + g;

            if (kt >= 2 * qt) {
                // diagonal region: unpack to f32, mask, f32 softmax path
                float c_[8][4];
                #pragma unroll
                for (int j = 0; j < 8; j++) {
                    float2 lo = __half22float2(*reinterpret_cast<__half2*>(&chh[j][0]));
                    float2 hi = __half22float2(*reinterpret_cast<__half2*>(&chh[j][1]));
                    c_[j][0] = lo.x; c_[j][1] = lo.y;
                    c_[j][2] = hi.x; c_[j][3] = hi.y;
                }
                #pragma unroll
                for (int j = 0; j < 8; j++) {
                    #pragma unroll
                    for (int e = 0; e < 4; e++) {
                        int col = kt * 64 + j * 8 + tg * 2 + (e & 1);
                        int row = q0 + warp * 16 + g + (e >> 1) * 8;
                        c_[j][e] = (col > row) ? NEG_INF : c_[j][e] * SCALE2;
                    }
                }
                float rx0 = NEG_INF, rx1 = NEG_INF;
                #pragma unroll
                for (int j = 0; j < 8; j++) {
                    rx0 = fmaxf(rx0, fmaxf(c_[j][0], c_[j][1]));
                    rx1 = fmaxf(rx1, fmaxf(c_[j][2], c_[j][3]));
                }
                rx0 = fmaxf(rx0, __shfl_xor_sync(0xffffffffu, rx0, 1));
                rx0 = fmaxf(rx0, __shfl_xor_sync(0xffffffffu, rx0, 2));
                rx1 = fmaxf(rx1, __shfl_xor_sync(0xffffffffu, rx1, 1));
                rx1 = fmaxf(rx1, __shfl_xor_sync(0xffffffffu, rx1, 2));
                mn0 = fmaxf(m0, rx0); mn1 = fmaxf(m1, rx1);
                al0 = ex2(m0 - mn0);  al1 = ex2(m1 - mn1);
                #pragma unroll
                for (int j = 0; j < 8; j++) {
                    *(uint32_t*)(sQP + rl * ALD + j * 8 + tg * 2) =
                        h2ex2(c_[j][0] - mn0, c_[j][1] - mn0);
                    *(uint32_t*)(sQP + (rl + 8) * ALD + j * 8 + tg * 2) =
                        h2ex2(c_[j][2] - mn1, c_[j][3] - mn1);
                }
            } else {
                // interior tile: packed fp16 softmax front-end
                __half2 h0[8], h1[8];
                __half2 mx0 = __float2half2_rn(NEG_INF), mx1 = mx0;
                #pragma unroll
                for (int j = 0; j < 8; j++) {
                    h0[j] = __hmul2(*reinterpret_cast<__half2*>(&chh[j][0]), sc2);
                    h1[j] = __hmul2(*reinterpret_cast<__half2*>(&chh[j][1]), sc2);
                    mx0 = __hmax2(mx0, h0[j]);
                    mx1 = __hmax2(mx1, h1[j]);
                }
                float rx0 = fmaxf(__low2float(mx0), __high2float(mx0));
                float rx1 = fmaxf(__low2float(mx1), __high2float(mx1));
                rx0 = fmaxf(rx0, __shfl_xor_sync(0xffffffffu, rx0, 1));
                rx0 = fmaxf(rx0, __shfl_xor_sync(0xffffffffu, rx0, 2));
                rx1 = fmaxf(rx1, __shfl_xor_sync(0xffffffffu, rx1, 1));
                rx1 = fmaxf(rx1, __shfl_xor_sync(0xffffffffu, rx1, 2));
                mn0 = fmaxf(m0, rx0); mn1 = fmaxf(m1, rx1);
                al0 = ex2(m0 - mn0);  al1 = ex2(m1 - mn1);
                __half2 mnh0 = __float2half2_rn(mn0);
                __half2 mnh1 = __float2half2_rn(mn1);
                #pragma unroll
                for (int j = 0; j < 8; j++) {
                    __half2 d0 = __hsub2(h0[j], mnh0);
                    __half2 d1 = __hsub2(h1[j], mnh1);
                    *(uint32_t*)(sQP + rl * ALD + j * 8 + tg * 2) =
                        h2ex2u(*reinterpret_cast<uint32_t*>(&d0));
                    *(uint32_t*)(sQP + (rl + 8) * ALD + j * 8 + tg * 2) =
                        h2ex2u(*reinterpret_cast<uint32_t*>(&d1));
                }
            }
            m0 = mn0; m1 = mn1;

            #pragma unroll
            for (int j = 0; j < 8; j++) {
                o[j][0] *= al0; o[j][1] *= al0;
                o[j][2] *= al1; o[j][3] *= al1;
            }
            __syncwarp();

            // O += P @ V ; row sums via ones-MMA
            float ls[4] = {0.f, 0.f, 0.f, 0.f};
            #pragma unroll
            for (int st = 0; st < 4; st++) {
                uint32_t pf[4];
                ldsm4(pf, pBase + (uint32_t)(st * 32));
                mma_f16(ls, pf[0], pf[1], pf[2], pf[3], ONES_H2, ONES_H2);
                #pragma unroll
                for (int jp = 0; jp < 4; jp++) {
                    uint32_t vf[4];
                    ldsm4t(vf, vB + (uint32_t)(st * 16 * ALD * 2 + jp * 32));
                    mma_f16(o[jp * 2],     pf[0], pf[1], pf[2], pf[3], vf[0], vf[1]);
                    mma_f16(o[jp * 2 + 1], pf[0], pf[1], pf[2], pf[3], vf[2], vf[3]);
                }
            }
            __syncwarp();

            l0 = l0 * al0 + ls[0];
            l1 = l1 * al1 + ls[2];
        }

        if (kt + 1 < tiles) {
            cp_wait<0>();
            __syncthreads();
        }
    }

    const float inv0 = 1.f / l0, inv1 = 1.f / l1;
    const int srow = q0 + warp * 16 + g;
    __half* out0 = g_attn + ((size_t)b * SEQ + srow) * DM + h * DH;
    __half* out1 = g_attn + ((size_t)b * SEQ + srow + 8) * DM + h * DH;
    #pragma unroll
    for (int j = 0; j < 8; j++) {
        int cl = j * 8 + tg * 2;
        *(__half2*)(out0 + cl) = __floats2half2_rn(o[j][0] * inv0, o[j][1] * inv0);
        *(__half2*)(out1 + cl) = __floats2half2_rn(o[j][2] * inv1, o[j][3] * inv1);
    }
}

// ---------------------------------------------------------------------------
// Launch
// ---------------------------------------------------------------------------
extern "C" void kernel_launch(void* const* d_in, const int* in_sizes, int n_in,
                              void* d_out, int out_size)
{
    (void)in_sizes; (void)n_in; (void)out_size;
    const float* x     = (const float*)d_in[0];
    const float* w_in  = (const float*)d_in[1];
    const float* b_in  = (const float*)d_in[2];
    const float* w_out = (const float*)d_in[3];
    const float* b_out = (const float*)d_in[4];
    float* out = (float*)d_out;

    __half *qkv, *attn, *xh, *winT, *woutT;
    cudaGetSymbolAddress((void**)&qkv,   g_qkv);
    cudaGetSymbolAddress((void**)&attn,  g_attn);
    cudaGetSymbolAddress((void**)&xh,    g_x);
    cudaGetSymbolAddress((void**)&winT,  g_winT);
    cudaGetSymbolAddress((void**)&woutT, g_woutT);

    const int M = BATCH * SEQ;  // 8192

    cudaFuncSetAttribute(gemm_tc<3 * DM, 1>, cudaFuncAttributeMaxDynamicSharedMemorySize, GEMM_SMEM);
    cudaFuncSetAttribute(gemm_tc<DM, 0>,     cudaFuncAttributeMaxDynamicSharedMemorySize, GEMM_SMEM);
    cudaFuncSetAttribute(attn_kernel, cudaFuncAttributeMaxDynamicSharedMemorySize, ATTN_SMEM);

    // 0) convert x to fp16; transpose+convert weights
    {
        int n4 = (M * DM) / 4;
        f2h_kernel<<<(n4 + 255) / 256, 256>>>(x, xh, n4);
        transpose_f2h_kernel<<<dim3((3 * DM) / 32, DM / 32), dim3(32, 8)>>>(
            w_in, winT, DM, 3 * DM);
        transpose_f2h_kernel<<<dim3(DM / 32, DM / 32), dim3(32, 8)>>>(
            w_out, woutT, DM, DM);
    }

    // 1) QKV projection (fp16 output)
    gemm_tc<3 * DM, 1><<<dim3((3 * DM) / 128, M / 128), 256, GEMM_SMEM>>>(
        xh, winT, b_in, qkv);

    // 2) causal flash attention (fp16 output)
    attn_kernel<<<dim3(SEQ / BQ, BATCH * NH), 256, ATTN_SMEM>>>();

    // 3) output projection (f32 output)
    gemm_tc<DM, 0><<<dim3(DM / 128, M / 128), 256, GEMM_SMEM>>>(
        attn, woutT, b_out, out);
}